// round 2
// baseline (speedup 1.0000x reference)
#include <cuda_runtime.h>
#include <cstdint>

// Problem constants
#define E_DIM 1024
#define FF_DIM 4096
#define NB 6
#define NWA 8
#define NWF 4
#define C_DIM 1000
#define B_DIM 4096
#define TPB 256   // threads per block (8 warps)

// Scratch state (device globals: allocation-free)
__device__ float g_h[E_DIM];      // post-LN2 h entering iteration i (written by kA block 0)
__device__ float g_h1[E_DIM];     // post-LN1 h (written by kB block 0)
__device__ float g_attn[E_DIM];   // attention output of iteration i
__device__ float g_f[E_DIM];      // FFN output of iteration i
__device__ __align__(16) float g_logits[C_DIM];

// ---------------------------------------------------------------------------
// Block-wide sum over 256 threads. Deterministic. `red` must hold >= 8 floats.
__device__ __forceinline__ float blockSum256(float v, float* red) {
    #pragma unroll
    for (int o = 16; o; o >>= 1) v += __shfl_xor_sync(0xffffffffu, v, o);
    int lane = threadIdx.x & 31, w = threadIdx.x >> 5;
    __syncthreads();
    if (lane == 0) red[w] = v;
    __syncthreads();
    float t = red[0];
    #pragma unroll
    for (int i = 1; i < 8; i++) t += red[i];
    return t;  // identical in all threads
}

// LayerNorm of (a + b) with gamma g / beta bb into shared sh[E_DIM].
// Two-pass (mean, then var) to match reference numerics. Ends synced.
__device__ __forceinline__ void ln_sum_into_shared(
    const float* __restrict__ a, const float* __restrict__ b,
    const float* __restrict__ g, const float* __restrict__ bb,
    float* sh, float* red)
{
    int tid = threadIdx.x;
    float x[4];
    float s = 0.f;
    #pragma unroll
    for (int c = 0; c < 4; c++) { int j = tid + TPB * c; x[c] = a[j] + b[j]; s += x[c]; }
    float mean = blockSum256(s, red) * (1.0f / E_DIM);
    float ss = 0.f;
    #pragma unroll
    for (int c = 0; c < 4; c++) { float d = x[c] - mean; ss += d * d; }
    float var = blockSum256(ss, red) * (1.0f / E_DIM);
    float inv = rsqrtf(var + 1e-5f);
    #pragma unroll
    for (int c = 0; c < 4; c++) {
        int j = tid + TPB * c;
        sh[j] = (x[c] - mean) * inv * g[j] + bb[j];
    }
    __syncthreads();
}

__device__ __forceinline__ float warpDot1024(const float4* __restrict__ row,
                                             const float4* __restrict__ vec, int lane) {
    float acc = 0.f;
    #pragma unroll
    for (int k4 = lane; k4 < E_DIM / 4; k4 += 32) {
        float4 a = row[k4]; float4 b = vec[k4];
        acc += a.x * b.x + a.y * b.y + a.z * b.z + a.w * b.w;
    }
    #pragma unroll
    for (int o = 16; o; o >>= 1) acc += __shfl_xor_sync(0xffffffffu, acc, o);
    return acc;
}

// ---------------------------------------------------------------------------
// Kernel A: h = (iter==0 ? h0 : LN2(h1_prev + f_prev)); v = Wv[i] @ cos(h[:8]+phi_q[i]);
//           attn = Wo[i] @ v.   Grid: 128 blocks x 256 threads; warp per Wo row.
__global__ void __launch_bounds__(TPB)
kA(const float* __restrict__ Wv, const float* __restrict__ Wo,
   const float* __restrict__ phi_q,
   const float* __restrict__ ln2g, const float* __restrict__ ln2b,
   int iter)
{
    __shared__ float sh_h[E_DIM];
    __shared__ float sh_v[E_DIM];
    __shared__ float red[8];
    __shared__ float s_proj[NWA];
    int tid = threadIdx.x;

    if (iter == 0) {
        #pragma unroll
        for (int c = 0; c < 4; c++) { int j = tid + TPB * c; sh_h[j] = (j & 1) ? 2.0f : 1.0f; }
        __syncthreads();
    } else {
        ln_sum_into_shared(g_h1, g_f, ln2g + (size_t)(iter - 1) * E_DIM,
                           ln2b + (size_t)(iter - 1) * E_DIM, sh_h, red);
    }

    if (tid < NWA) s_proj[tid] = cosf(sh_h[tid] + phi_q[iter * NWA + tid]);
    __syncthreads();

    float p[NWA];
    #pragma unroll
    for (int w = 0; w < NWA; w++) p[w] = s_proj[w];

    // v[e] = sum_w Wv[i][e,w] * proj[w]
    const float4* wvb = reinterpret_cast<const float4*>(Wv + (size_t)iter * E_DIM * NWA);
    #pragma unroll
    for (int c = 0; c < 4; c++) {
        int j = tid + TPB * c;
        float4 a = wvb[j * 2], b = wvb[j * 2 + 1];
        sh_v[j] = a.x * p[0] + a.y * p[1] + a.z * p[2] + a.w * p[3]
                + b.x * p[4] + b.y * p[5] + b.z * p[6] + b.w * p[7];
    }
    __syncthreads();

    if (blockIdx.x == 0) {
        #pragma unroll
        for (int c = 0; c < 4; c++) { int j = tid + TPB * c; g_h[j] = sh_h[j]; }
    }

    int w = tid >> 5, lane = tid & 31;
    int r = blockIdx.x * 8 + w;  // 128 blocks * 8 warps = 1024 rows
    const float4* row = reinterpret_cast<const float4*>(Wo + ((size_t)iter * E_DIM + r) * E_DIM);
    float acc = warpDot1024(row, reinterpret_cast<const float4*>(sh_v), lane);
    if (lane == 0) g_attn[r] = acc;
}

// ---------------------------------------------------------------------------
// Kernel B: h1 = LN1(h + attn); f1 = relu(W1[i] @ (cos(h1[:4])*cos(phi_f[i])));
//           f = W2[i] @ f1.   Grid: 128 blocks x 256 threads; warp per W2 row.
__global__ void __launch_bounds__(TPB)
kB(const float* __restrict__ W1, const float* __restrict__ W2,
   const float* __restrict__ phi_f,
   const float* __restrict__ ln1g, const float* __restrict__ ln1b,
   int iter)
{
    __shared__ float sh_h1[E_DIM];
    __shared__ float sh_f1[FF_DIM];
    __shared__ float red[8];
    __shared__ float s_m[NWF];
    int tid = threadIdx.x;

    ln_sum_into_shared(g_h, g_attn, ln1g + (size_t)iter * E_DIM,
                       ln1b + (size_t)iter * E_DIM, sh_h1, red);

    if (tid < NWF) s_m[tid] = cosf(sh_h1[tid]) * cosf(phi_f[iter * NWF + tid]);
    __syncthreads();

    float m0 = s_m[0], m1 = s_m[1], m2 = s_m[2], m3 = s_m[3];

    const float4* w1b = reinterpret_cast<const float4*>(W1 + (size_t)iter * FF_DIM * NWF);
    #pragma unroll
    for (int c = 0; c < FF_DIM / TPB; c++) {
        int k = tid + TPB * c;
        float4 w4 = w1b[k];
        float t = w4.x * m0 + w4.y * m1 + w4.z * m2 + w4.w * m3;
        sh_f1[k] = fmaxf(t, 0.f);
    }
    __syncthreads();

    if (blockIdx.x == 0) {
        #pragma unroll
        for (int c = 0; c < 4; c++) { int j = tid + TPB * c; g_h1[j] = sh_h1[j]; }
    }

    int w = tid >> 5, lane = tid & 31;
    int r = blockIdx.x * 8 + w;
    const float4* row = reinterpret_cast<const float4*>(W2 + ((size_t)iter * E_DIM + r) * FF_DIM);
    const float4* f14 = reinterpret_cast<const float4*>(sh_f1);
    float acc = 0.f;
    #pragma unroll 8
    for (int k4 = lane; k4 < FF_DIM / 4; k4 += 32) {
        float4 a = row[k4]; float4 b = f14[k4];
        acc += a.x * b.x + a.y * b.y + a.z * b.z + a.w * b.w;
    }
    #pragma unroll
    for (int o = 16; o; o >>= 1) acc += __shfl_xor_sync(0xffffffffu, acc, o);
    if (lane == 0) g_f[r] = acc;
}

// ---------------------------------------------------------------------------
// Kernel C: h_final = LN2(h1 + f) (iter 5 params); logits = Wc @ h_final + bc.
// Grid: 125 blocks x 256 threads; warp per Wc row (125*8 = 1000).
__global__ void __launch_bounds__(TPB)
kC(const float* __restrict__ Wc, const float* __restrict__ bc,
   const float* __restrict__ ln2g, const float* __restrict__ ln2b)
{
    __shared__ float sh_h[E_DIM];
    __shared__ float red[8];
    int tid = threadIdx.x;

    ln_sum_into_shared(g_h1, g_f, ln2g + (size_t)(NB - 1) * E_DIM,
                       ln2b + (size_t)(NB - 1) * E_DIM, sh_h, red);

    int w = tid >> 5, lane = tid & 31;
    int r = blockIdx.x * 8 + w;  // 0..999
    const float4* row = reinterpret_cast<const float4*>(Wc + (size_t)r * E_DIM);
    float acc = warpDot1024(row, reinterpret_cast<const float4*>(sh_h), lane);
    if (lane == 0) g_logits[r] = acc + bc[r];
}

// ---------------------------------------------------------------------------
// Kernel D: broadcast logits row across all B rows of output. float4 stores.
// Stage logits in shared once per block; pure 16 MB STG stream after that.
__global__ void __launch_bounds__(TPB)
kD(float4* __restrict__ out)
{
    __shared__ __align__(16) float s_lg[C_DIM];
    int tid = threadIdx.x;
    #pragma unroll
    for (int c = 0; c < 4; c++) {
        int j = tid + TPB * c;
        if (j < C_DIM) s_lg[j] = g_logits[j];
    }
    __syncthreads();

    const int total4 = B_DIM * C_DIM / 4;  // 4,096,000 floats / 4 = 1,024,000
    const float4* lg = reinterpret_cast<const float4*>(s_lg);
    int stride = gridDim.x * blockDim.x;
    for (int i = blockIdx.x * blockDim.x + tid; i < total4; i += stride) {
        out[i] = lg[i % (C_DIM / 4)];
    }
}

// ---------------------------------------------------------------------------
extern "C" void kernel_launch(void* const* d_in, const int* in_sizes, int n_in,
                              void* d_out, int out_size)
{
    // metadata order:
    // 0:x 1:Wq 2:Wk 3:Wv 4:Wo 5:phi_q 6:W1 7:W2 8:phi_f
    // 9:ln1_g 10:ln1_b 11:ln2_g 12:ln2_b 13:Wc 14:bc
    const float* Wv    = (const float*)d_in[3];
    const float* Wo    = (const float*)d_in[4];
    const float* phi_q = (const float*)d_in[5];
    const float* W1    = (const float*)d_in[6];
    const float* W2    = (const float*)d_in[7];
    const float* phi_f = (const float*)d_in[8];
    const float* ln1g  = (const float*)d_in[9];
    const float* ln1b  = (const float*)d_in[10];
    const float* ln2g  = (const float*)d_in[11];
    const float* ln2b  = (const float*)d_in[12];
    const float* Wc    = (const float*)d_in[13];
    const float* bc    = (const float*)d_in[14];
    float* out = (float*)d_out;

    for (int i = 0; i < NB; i++) {
        kA<<<128, TPB>>>(Wv, Wo, phi_q, ln2g, ln2b, i);
        kB<<<128, TPB>>>(W1, W2, phi_f, ln1g, ln1b, i);
    }
    kC<<<125, TPB>>>(Wc, bc, ln2g, ln2b);
    kD<<<2048, TPB>>>((float4*)out);
}

// round 3
// speedup vs baseline: 1.2005x; 1.2005x over previous
#include <cuda_runtime.h>
#include <cstdint>

// Problem constants
#define E_DIM 1024
#define FF_DIM 4096
#define NB 6
#define NWA 8
#define NWF 4
#define C_DIM 1000
#define B_DIM 4096
#define NT 512          // threads per block (16 warps)

// Cross-block state (device globals: allocation-free). Written with release
// fence + grid barrier; read with __ldcg (L2) so stale L1 is never an issue.
__device__ float g_attn[E_DIM];
__device__ float g_f[E_DIM];
__device__ __align__(16) float g_logits[1024];   // 1000 used, padded
__device__ unsigned g_barCount;                  // monotonic across launches/replays

// ---------------------------------------------------------------------------
__device__ __forceinline__ float warpRed(float v) {
    #pragma unroll
    for (int o = 16; o; o >>= 1) v += __shfl_xor_sync(0xffffffffu, v, o);
    return v;
}

// Block-wide sum over NT=512 threads; result identical in all threads.
// red must hold >= 16 floats. Contains syncthreads (uniform call sites only).
__device__ __forceinline__ float blockSumAll(float v, float* red) {
    v = warpRed(v);
    int lane = threadIdx.x & 31, w = threadIdx.x >> 5;
    __syncthreads();
    if (lane == 0) red[w] = v;
    __syncthreads();
    float t = red[0];
    #pragma unroll
    for (int i = 1; i < 16; i++) t += red[i];
    return t;
}

// Grid-wide barrier: monotonic counter (safe across graph replays).
// Release: every thread fences before arrival. Acquire: post-wait reads of
// mutable state use __ldcg, so no L1 flush needed on the reader side.
__device__ __forceinline__ void grid_barrier() {
    __threadfence();
    __syncthreads();
    if (threadIdx.x == 0) {
        unsigned nb = gridDim.x;
        unsigned arrival = atomicAdd(&g_barCount, 1u);
        unsigned target = (arrival / nb + 1u) * nb;
        volatile unsigned* p = &g_barCount;
        while (*p < target) { }
    }
    __syncthreads();
}

// ---------------------------------------------------------------------------
// Single persistent kernel. grid = #SMs, 1 CTA/SM (co-resident).
__global__ void __launch_bounds__(NT, 1)
fused(const float* __restrict__ Wv, const float* __restrict__ Wo,
      const float* __restrict__ phi_q,
      const float* __restrict__ W1, const float* __restrict__ W2,
      const float* __restrict__ phi_f,
      const float* __restrict__ ln1g, const float* __restrict__ ln1b,
      const float* __restrict__ ln2g, const float* __restrict__ ln2b,
      const float* __restrict__ Wc, const float* __restrict__ bc,
      float4* __restrict__ out)
{
    __shared__ float sh_h[E_DIM];                 // h, then h1 (in place)
    __shared__ __align__(16) float sh_v[E_DIM];   // attention v vector
    __shared__ __align__(16) float sh_f1[FF_DIM]; // FFN hidden / logits staging
    __shared__ float red[64];                     // 4 rows x 16 warp sums
    __shared__ float s_small[8];

    const int tid = threadIdx.x, bid = blockIdx.x, nb = gridDim.x;
    const int lane = tid & 31, wid = tid >> 5;

    for (int it = 0; it < NB; ++it) {
        // ---- h = (it==0 ? 1+pe0 : LN2_{it-1}(h1_prev + f_prev)) into sh_h ----
        if (it == 0) {
            sh_h[tid]      = (tid & 1) ? 2.0f : 1.0f;
            sh_h[tid + NT] = (tid & 1) ? 2.0f : 1.0f;   // same parity
            __syncthreads();
        } else {
            float x0 = sh_h[tid]      + __ldcg(&g_f[tid]);
            float x1 = sh_h[tid + NT] + __ldcg(&g_f[tid + NT]);
            float mean = blockSumAll(x0 + x1, red) * (1.0f / E_DIM);
            float d0 = x0 - mean, d1 = x1 - mean;
            float var = blockSumAll(d0 * d0 + d1 * d1, red) * (1.0f / E_DIM);
            float inv = rsqrtf(var + 1e-5f);
            const float* g = ln2g + (size_t)(it - 1) * E_DIM;
            const float* b = ln2b + (size_t)(it - 1) * E_DIM;
            sh_h[tid]      = d0 * inv * g[tid]      + b[tid];
            sh_h[tid + NT] = d1 * inv * g[tid + NT] + b[tid + NT];
            __syncthreads();
        }

        // ---- proj = cos(h[:8] + phi_q[it]) ----
        if (tid < NWA) s_small[tid] = cosf(sh_h[tid] + phi_q[it * NWA + tid]);
        __syncthreads();
        {
            float p[NWA];
            #pragma unroll
            for (int w = 0; w < NWA; w++) p[w] = s_small[w];
            // v[e] = Wv[it][e,:] . proj   (Wv rows of 8 = 2 float4)
            const float4* wv4 = reinterpret_cast<const float4*>(Wv + (size_t)it * E_DIM * NWA);
            #pragma unroll
            for (int c = 0; c < 2; c++) {
                int j = tid + NT * c;
                float4 a = wv4[2 * j], b = wv4[2 * j + 1];
                sh_v[j] = a.x * p[0] + a.y * p[1] + a.z * p[2] + a.w * p[3]
                        + b.x * p[4] + b.y * p[5] + b.z * p[6] + b.w * p[7];
            }
        }
        __syncthreads();

        // ---- attn = Wo[it] @ v : block-per-row, 4-row preload batches ----
        {
            const float* WoB = Wo + (size_t)it * E_DIM * E_DIM;
            const float4* v4 = reinterpret_cast<const float4*>(sh_v);
            for (int jb = 0;; jb += 4) {
                int rf = bid + nb * jb;
                if (rf >= E_DIM) break;
                float4 a[4]; float pr[4];
                #pragma unroll
                for (int gidx = 0; gidx < 4; gidx++) {
                    int rr = bid + nb * (jb + gidx);
                    if (rr < E_DIM && tid < 256)
                        a[gidx] = reinterpret_cast<const float4*>(WoB + (size_t)rr * E_DIM)[tid];
                }
                #pragma unroll
                for (int gidx = 0; gidx < 4; gidx++) {
                    int rr = bid + nb * (jb + gidx);
                    if (rr < E_DIM && tid < 256) {
                        float4 b = v4[tid];
                        pr[gidx] = a[gidx].x * b.x + a[gidx].y * b.y
                                 + a[gidx].z * b.z + a[gidx].w * b.w;
                    } else pr[gidx] = 0.f;
                    pr[gidx] = warpRed(pr[gidx]);
                }
                __syncthreads();
                if (lane == 0) {
                    #pragma unroll
                    for (int gidx = 0; gidx < 4; gidx++) red[gidx * 16 + wid] = pr[gidx];
                }
                __syncthreads();
                if (tid < 4) {
                    int rr = bid + nb * (jb + tid);
                    if (rr < E_DIM) {
                        float s = 0.f;
                        #pragma unroll
                        for (int k = 0; k < 16; k++) s += red[tid * 16 + k];
                        g_attn[rr] = s;
                    }
                }
            }
        }
        grid_barrier();

        // ---- h1 = LN1_it(h + attn) into sh_h (in place) ----
        {
            float x0 = sh_h[tid]      + __ldcg(&g_attn[tid]);
            float x1 = sh_h[tid + NT] + __ldcg(&g_attn[tid + NT]);
            float mean = blockSumAll(x0 + x1, red) * (1.0f / E_DIM);
            float d0 = x0 - mean, d1 = x1 - mean;
            float var = blockSumAll(d0 * d0 + d1 * d1, red) * (1.0f / E_DIM);
            float inv = rsqrtf(var + 1e-5f);
            const float* g = ln1g + (size_t)it * E_DIM;
            const float* b = ln1b + (size_t)it * E_DIM;
            sh_h[tid]      = d0 * inv * g[tid]      + b[tid];
            sh_h[tid + NT] = d1 * inv * g[tid + NT] + b[tid + NT];
            __syncthreads();
        }

        // ---- m = cos(h1[:4])*cos(phi_f[it]); f1 = relu(W1[it] @ m) ----
        if (tid < NWF) s_small[tid] = cosf(sh_h[tid]) * cosf(phi_f[it * NWF + tid]);
        __syncthreads();
        {
            float m0 = s_small[0], m1 = s_small[1], m2 = s_small[2], m3 = s_small[3];
            const float4* w14 = reinterpret_cast<const float4*>(W1 + (size_t)it * FF_DIM * NWF);
            #pragma unroll
            for (int c = 0; c < FF_DIM / NT; c++) {
                int k = tid + NT * c;
                float4 w = w14[k];
                sh_f1[k] = fmaxf(w.x * m0 + w.y * m1 + w.z * m2 + w.w * m3, 0.f);
            }
        }
        __syncthreads();

        // ---- f = W2[it] @ f1 : block-per-row, 4-row preload batches ----
        {
            const float* W2B = W2 + (size_t)it * E_DIM * FF_DIM;
            const float4* f14 = reinterpret_cast<const float4*>(sh_f1);
            float4 fb0 = f14[tid], fb1 = f14[tid + NT];
            for (int jb = 0;; jb += 4) {
                int rf = bid + nb * jb;
                if (rf >= E_DIM) break;
                float4 a[4][2]; float pr[4];
                #pragma unroll
                for (int gidx = 0; gidx < 4; gidx++) {
                    int rr = bid + nb * (jb + gidx);
                    if (rr < E_DIM) {
                        const float4* row = reinterpret_cast<const float4*>(W2B + (size_t)rr * FF_DIM);
                        a[gidx][0] = row[tid];
                        a[gidx][1] = row[tid + NT];
                    }
                }
                #pragma unroll
                for (int gidx = 0; gidx < 4; gidx++) {
                    int rr = bid + nb * (jb + gidx);
                    if (rr < E_DIM) {
                        pr[gidx] = a[gidx][0].x * fb0.x + a[gidx][0].y * fb0.y
                                 + a[gidx][0].z * fb0.z + a[gidx][0].w * fb0.w
                                 + a[gidx][1].x * fb1.x + a[gidx][1].y * fb1.y
                                 + a[gidx][1].z * fb1.z + a[gidx][1].w * fb1.w;
                    } else pr[gidx] = 0.f;
                    pr[gidx] = warpRed(pr[gidx]);
                }
                __syncthreads();
                if (lane == 0) {
                    #pragma unroll
                    for (int gidx = 0; gidx < 4; gidx++) red[gidx * 16 + wid] = pr[gidx];
                }
                __syncthreads();
                if (tid < 4) {
                    int rr = bid + nb * (jb + tid);
                    if (rr < E_DIM) {
                        float s = 0.f;
                        #pragma unroll
                        for (int k = 0; k < 16; k++) s += red[tid * 16 + k];
                        g_f[rr] = s;
                    }
                }
            }
        }
        grid_barrier();
    }

    // ---- h_final = LN2_{NB-1}(h1 + f) into sh_h ----
    {
        float x0 = sh_h[tid]      + __ldcg(&g_f[tid]);
        float x1 = sh_h[tid + NT] + __ldcg(&g_f[tid + NT]);
        float mean = blockSumAll(x0 + x1, red) * (1.0f / E_DIM);
        float d0 = x0 - mean, d1 = x1 - mean;
        float var = blockSumAll(d0 * d0 + d1 * d1, red) * (1.0f / E_DIM);
        float inv = rsqrtf(var + 1e-5f);
        const float* g = ln2g + (size_t)(NB - 1) * E_DIM;
        const float* b = ln2b + (size_t)(NB - 1) * E_DIM;
        sh_h[tid]      = d0 * inv * g[tid]      + b[tid];
        sh_h[tid + NT] = d1 * inv * g[tid + NT] + b[tid + NT];
        __syncthreads();
    }

    // ---- logits = Wc @ h_final + bc : block-per-row batches ----
    {
        const float4* h4 = reinterpret_cast<const float4*>(sh_h);
        for (int jb = 0;; jb += 4) {
            int rf = bid + nb * jb;
            if (rf >= C_DIM) break;
            float4 a[4]; float pr[4];
            #pragma unroll
            for (int gidx = 0; gidx < 4; gidx++) {
                int rr = bid + nb * (jb + gidx);
                if (rr < C_DIM && tid < 256)
                    a[gidx] = reinterpret_cast<const float4*>(Wc + (size_t)rr * E_DIM)[tid];
            }
            #pragma unroll
            for (int gidx = 0; gidx < 4; gidx++) {
                int rr = bid + nb * (jb + gidx);
                if (rr < C_DIM && tid < 256) {
                    float4 b = h4[tid];
                    pr[gidx] = a[gidx].x * b.x + a[gidx].y * b.y
                             + a[gidx].z * b.z + a[gidx].w * b.w;
                } else pr[gidx] = 0.f;
                pr[gidx] = warpRed(pr[gidx]);
            }
            __syncthreads();
            if (lane == 0) {
                #pragma unroll
                for (int gidx = 0; gidx < 4; gidx++) red[gidx * 16 + wid] = pr[gidx];
            }
            __syncthreads();
            if (tid < 4) {
                int rr = bid + nb * (jb + tid);
                if (rr < C_DIM) {
                    float s = 0.f;
                    #pragma unroll
                    for (int k = 0; k < 16; k++) s += red[tid * 16 + k];
                    g_logits[rr] = s + bc[rr];
                }
            }
        }
    }
    grid_barrier();

    // ---- broadcast logits row across all B rows of out (16 MB stores) ----
    #pragma unroll
    for (int c = 0; c < 2; c++) {
        int k = tid + NT * c;
        if (k < C_DIM) sh_f1[k] = __ldcg(&g_logits[k]);
    }
    __syncthreads();
    {
        const float4* lg = reinterpret_cast<const float4*>(sh_f1);
        const int total4 = B_DIM * C_DIM / 4;   // 1,024,000
        const int stride = nb * NT;
        for (int i = bid * NT + tid; i < total4; i += stride)
            out[i] = lg[i % (C_DIM / 4)];
    }
}

// ---------------------------------------------------------------------------
extern "C" void kernel_launch(void* const* d_in, const int* in_sizes, int n_in,
                              void* d_out, int out_size)
{
    // metadata order:
    // 0:x 1:Wq 2:Wk 3:Wv 4:Wo 5:phi_q 6:W1 7:W2 8:phi_f
    // 9:ln1_g 10:ln1_b 11:ln2_g 12:ln2_b 13:Wc 14:bc
    const float* Wv    = (const float*)d_in[3];
    const float* Wo    = (const float*)d_in[4];
    const float* phi_q = (const float*)d_in[5];
    const float* W1    = (const float*)d_in[6];
    const float* W2    = (const float*)d_in[7];
    const float* phi_f = (const float*)d_in[8];
    const float* ln1g  = (const float*)d_in[9];
    const float* ln1b  = (const float*)d_in[10];
    const float* ln2g  = (const float*)d_in[11];
    const float* ln2b  = (const float*)d_in[12];
    const float* Wc    = (const float*)d_in[13];
    const float* bc    = (const float*)d_in[14];

    int dev = 0;
    cudaGetDevice(&dev);
    int sms = 148;
    cudaDeviceGetAttribute(&sms, cudaDevAttrMultiProcessorCount, dev);

    fused<<<sms, NT>>>(Wv, Wo, phi_q, W1, W2, phi_f,
                       ln1g, ln1b, ln2g, ln2b, Wc, bc, (float4*)d_out);
}

// round 4
// speedup vs baseline: 1.4166x; 1.1800x over previous
#include <cuda_runtime.h>
#include <cstdint>

// Problem constants
#define E_DIM 1024
#define FF_DIM 4096
#define NB 6
#define NWA 8
#define NWF 4
#define C_DIM 1000
#define B_DIM 4096
#define NT 512          // threads per block (16 warps)
#define MAXR 7          // max rows per CTA for E_DIM/C_DIM split over >=147 blocks

// Cross-block state (device globals: allocation-free).
__device__ float g_attn[E_DIM];
__device__ float g_f[E_DIM];
__device__ __align__(16) float g_logits[1024];   // 1000 used, padded
__device__ unsigned g_barCount;                  // monotonic across launches/replays

// Dynamic smem layout (float offsets)
#define OFF_H    0
#define OFF_V    1024
#define OFF_F1   2048
#define OFF_W2   6144                    // 7*4096 = 28672
#define OFF_WO   (OFF_W2 + MAXR*FF_DIM)  // 34816, 7*1024
#define OFF_WC   (OFF_WO + MAXR*E_DIM)   // 41984, 7*1024
#define OFF_RED  (OFF_WC + MAXR*E_DIM)   // 49152
#define OFF_SM   (OFF_RED + 64)          // 49216
#define SMEM_FLOATS (OFF_SM + 8)         // 49224
#define SMEM_BYTES (SMEM_FLOATS * 4)     // 196896

// ---------------------------------------------------------------------------
__device__ __forceinline__ float warpRed(float v) {
    #pragma unroll
    for (int o = 16; o; o >>= 1) v += __shfl_xor_sync(0xffffffffu, v, o);
    return v;
}

__device__ __forceinline__ float blockSumAll(float v, float* red) {
    v = warpRed(v);
    int lane = threadIdx.x & 31, w = threadIdx.x >> 5;
    __syncthreads();
    if (lane == 0) red[w] = v;
    __syncthreads();
    float t = red[0];
    #pragma unroll
    for (int i = 1; i < 16; i++) t += red[i];
    return t;
}

// Grid-wide barrier: monotonic counter (safe across graph replays).
__device__ __forceinline__ void grid_barrier() {
    __threadfence();
    __syncthreads();
    if (threadIdx.x == 0) {
        unsigned nb = gridDim.x;
        unsigned arrival = atomicAdd(&g_barCount, 1u);
        unsigned target = (arrival / nb + 1u) * nb;
        volatile unsigned* p = &g_barCount;
        while (*p < target) { }
    }
    __syncthreads();
}

__device__ __forceinline__ void cp16(uint32_t saddr, const void* g) {
    asm volatile("cp.async.cg.shared.global [%0], [%1], 16;" :: "r"(saddr), "l"(g));
}

// Stream nrows rows (row r = global row bid + nb*r, rowStrideG floats each,
// row4 float4s kept per row) into a contiguous smem tile via cp.async.
__device__ __forceinline__ void fill_tile(float* sh, const float* gbase,
                                          int nrows, int row4, int rowStrideG,
                                          int bid, int nb) {
    int chunks = nrows * row4;
    uint32_t sbase = (uint32_t)__cvta_generic_to_shared(sh);
    for (int c = threadIdx.x; c < chunks; c += NT) {
        int r = c / row4;
        int off = c - r * row4;
        const float* g = gbase + (size_t)(bid + nb * r) * rowStrideG + off * 4;
        cp16(sbase + (uint32_t)c * 16u, g);
    }
}

// ---------------------------------------------------------------------------
__global__ void __launch_bounds__(NT, 1)
fused(const float* __restrict__ Wv, const float* __restrict__ Wo,
      const float* __restrict__ phi_q,
      const float* __restrict__ W1, const float* __restrict__ W2,
      const float* __restrict__ phi_f,
      const float* __restrict__ ln1g, const float* __restrict__ ln1b,
      const float* __restrict__ ln2g, const float* __restrict__ ln2b,
      const float* __restrict__ Wc, const float* __restrict__ bc,
      float4* __restrict__ out)
{
    extern __shared__ float sm[];
    float* sh_h   = sm + OFF_H;
    float* sh_v   = sm + OFF_V;
    float* sh_f1  = sm + OFF_F1;
    float* w2t    = sm + OFF_W2;
    float* wot    = sm + OFF_WO;
    float* wct    = sm + OFF_WC;
    float* red    = sm + OFF_RED;
    float* s_small= sm + OFF_SM;

    const int tid = threadIdx.x, bid = blockIdx.x, nb = gridDim.x;
    const int lane = tid & 31, wid = tid >> 5;

    // rows this CTA owns for 1024-row and 1000-row matvecs
    const int nrowsE = (E_DIM - bid + nb - 1) / nb;   // 6 or 7
    const int nrowsC = (C_DIM - bid + nb - 1) / nb;   // 6 or 7

    for (int it = 0; it < NB; ++it) {
        // ---- kick off weight streams for THIS iteration (async into smem) ----
        fill_tile(wot, Wo + (size_t)it * E_DIM * E_DIM, nrowsE, E_DIM / 4, E_DIM, bid, nb);
        asm volatile("cp.async.commit_group;" ::: "memory");
        if (it == NB - 1) {
            fill_tile(wct, Wc, nrowsC, E_DIM / 4, E_DIM, bid, nb);
            asm volatile("cp.async.commit_group;" ::: "memory");
        }
        fill_tile(w2t, W2 + (size_t)it * E_DIM * FF_DIM, nrowsE, FF_DIM / 4, FF_DIM, bid, nb);
        asm volatile("cp.async.commit_group;" ::: "memory");

        // ---- h = (it==0 ? 1+pe0 : LN2_{it-1}(h1_prev + f_prev)) ----
        if (it == 0) {
            sh_h[tid]      = (tid & 1) ? 2.0f : 1.0f;
            sh_h[tid + NT] = (tid & 1) ? 2.0f : 1.0f;
            __syncthreads();
        } else {
            float x0 = sh_h[tid]      + __ldcg(&g_f[tid]);
            float x1 = sh_h[tid + NT] + __ldcg(&g_f[tid + NT]);
            float mean = blockSumAll(x0 + x1, red) * (1.0f / E_DIM);
            float d0 = x0 - mean, d1 = x1 - mean;
            float var = blockSumAll(d0 * d0 + d1 * d1, red) * (1.0f / E_DIM);
            float inv = rsqrtf(var + 1e-5f);
            const float* g = ln2g + (size_t)(it - 1) * E_DIM;
            const float* b = ln2b + (size_t)(it - 1) * E_DIM;
            sh_h[tid]      = d0 * inv * g[tid]      + b[tid];
            sh_h[tid + NT] = d1 * inv * g[tid + NT] + b[tid + NT];
            __syncthreads();
        }

        // ---- proj = cos(h[:8] + phi_q[it]); v = Wv[it] @ proj ----
        if (tid < NWA) s_small[tid] = cosf(sh_h[tid] + phi_q[it * NWA + tid]);
        __syncthreads();
        {
            float p[NWA];
            #pragma unroll
            for (int w = 0; w < NWA; w++) p[w] = s_small[w];
            const float4* wv4 = reinterpret_cast<const float4*>(Wv + (size_t)it * E_DIM * NWA);
            #pragma unroll
            for (int c = 0; c < 2; c++) {
                int j = tid + NT * c;
                float4 a = wv4[2 * j], b = wv4[2 * j + 1];
                sh_v[j] = a.x * p[0] + a.y * p[1] + a.z * p[2] + a.w * p[3]
                        + b.x * p[4] + b.y * p[5] + b.z * p[6] + b.w * p[7];
            }
        }
        __syncthreads();

        // ---- wait Wo tile; attn rows from smem (warp per row) ----
        if (it == NB - 1) asm volatile("cp.async.wait_group 2;" ::: "memory");
        else              asm volatile("cp.async.wait_group 1;" ::: "memory");
        __syncthreads();
        if (wid < nrowsE) {
            const float4* row = reinterpret_cast<const float4*>(wot + wid * E_DIM);
            const float4* v4  = reinterpret_cast<const float4*>(sh_v);
            float acc = 0.f;
            #pragma unroll
            for (int k = 0; k < 8; k++) {
                float4 a = row[lane + 32 * k]; float4 b = v4[lane + 32 * k];
                acc += a.x * b.x + a.y * b.y + a.z * b.z + a.w * b.w;
            }
            acc = warpRed(acc);
            if (lane == 0) g_attn[bid + nb * wid] = acc;
        }
        grid_barrier();

        // ---- h1 = LN1_it(h + attn) ----
        {
            float x0 = sh_h[tid]      + __ldcg(&g_attn[tid]);
            float x1 = sh_h[tid + NT] + __ldcg(&g_attn[tid + NT]);
            float mean = blockSumAll(x0 + x1, red) * (1.0f / E_DIM);
            float d0 = x0 - mean, d1 = x1 - mean;
            float var = blockSumAll(d0 * d0 + d1 * d1, red) * (1.0f / E_DIM);
            float inv = rsqrtf(var + 1e-5f);
            const float* g = ln1g + (size_t)it * E_DIM;
            const float* b = ln1b + (size_t)it * E_DIM;
            sh_h[tid]      = d0 * inv * g[tid]      + b[tid];
            sh_h[tid + NT] = d1 * inv * g[tid + NT] + b[tid + NT];
            __syncthreads();
        }

        // ---- m = cos(h1[:4])*cos(phi_f[it]); f1 = relu(W1[it] @ m) ----
        if (tid < NWF) s_small[tid] = cosf(sh_h[tid]) * cosf(phi_f[it * NWF + tid]);
        __syncthreads();
        {
            float m0 = s_small[0], m1 = s_small[1], m2 = s_small[2], m3 = s_small[3];
            const float4* w14 = reinterpret_cast<const float4*>(W1 + (size_t)it * FF_DIM * NWF);
            #pragma unroll
            for (int c = 0; c < FF_DIM / NT; c++) {
                int k = tid + NT * c;
                float4 w = w14[k];
                sh_f1[k] = fmaxf(w.x * m0 + w.y * m1 + w.z * m2 + w.w * m3, 0.f);
            }
        }
        __syncthreads();

        // ---- wait W2 tile; f rows from smem (warp per row) ----
        asm volatile("cp.async.wait_group 0;" ::: "memory");
        __syncthreads();
        if (wid < nrowsE) {
            const float4* row = reinterpret_cast<const float4*>(w2t + wid * FF_DIM);
            const float4* f4  = reinterpret_cast<const float4*>(sh_f1);
            float acc = 0.f;
            #pragma unroll 8
            for (int k = 0; k < 32; k++) {
                float4 a = row[lane + 32 * k]; float4 b = f4[lane + 32 * k];
                acc += a.x * b.x + a.y * b.y + a.z * b.z + a.w * b.w;
            }
            acc = warpRed(acc);
            if (lane == 0) g_f[bid + nb * wid] = acc;
        }
        grid_barrier();
    }

    // ---- h_final = LN2_{NB-1}(h1 + f) ----
    {
        float x0 = sh_h[tid]      + __ldcg(&g_f[tid]);
        float x1 = sh_h[tid + NT] + __ldcg(&g_f[tid + NT]);
        float mean = blockSumAll(x0 + x1, red) * (1.0f / E_DIM);
        float d0 = x0 - mean, d1 = x1 - mean;
        float var = blockSumAll(d0 * d0 + d1 * d1, red) * (1.0f / E_DIM);
        float inv = rsqrtf(var + 1e-5f);
        const float* g = ln2g + (size_t)(NB - 1) * E_DIM;
        const float* b = ln2b + (size_t)(NB - 1) * E_DIM;
        sh_h[tid]      = d0 * inv * g[tid]      + b[tid];
        sh_h[tid + NT] = d1 * inv * g[tid + NT] + b[tid + NT];
        __syncthreads();
    }

    // ---- logits = Wc @ h_final + bc (Wc tile already resident in smem) ----
    if (wid < nrowsC) {
        const float4* row = reinterpret_cast<const float4*>(wct + wid * E_DIM);
        const float4* h4  = reinterpret_cast<const float4*>(sh_h);
        float acc = 0.f;
        #pragma unroll
        for (int k = 0; k < 8; k++) {
            float4 a = row[lane + 32 * k]; float4 b = h4[lane + 32 * k];
            acc += a.x * b.x + a.y * b.y + a.z * b.z + a.w * b.w;
        }
        acc = warpRed(acc);
        if (lane == 0) g_logits[bid + nb * wid] = acc + bc[bid + nb * wid];
    }
    grid_barrier();

    // ---- broadcast logits row across all B rows of out (16 MB stores) ----
    #pragma unroll
    for (int c = 0; c < 2; c++) {
        int k = tid + NT * c;
        if (k < C_DIM) sh_f1[k] = __ldcg(&g_logits[k]);
    }
    __syncthreads();
    {
        const float4* lg = reinterpret_cast<const float4*>(sh_f1);
        const int total4 = B_DIM * C_DIM / 4;   // 1,024,000
        const int stride = nb * NT;
        for (int i = bid * NT + tid; i < total4; i += stride)
            out[i] = lg[i % (C_DIM / 4)];
    }
}

// ---------------------------------------------------------------------------
extern "C" void kernel_launch(void* const* d_in, const int* in_sizes, int n_in,
                              void* d_out, int out_size)
{
    // metadata order:
    // 0:x 1:Wq 2:Wk 3:Wv 4:Wo 5:phi_q 6:W1 7:W2 8:phi_f
    // 9:ln1_g 10:ln1_b 11:ln2_g 12:ln2_b 13:Wc 14:bc
    const float* Wv    = (const float*)d_in[3];
    const float* Wo    = (const float*)d_in[4];
    const float* phi_q = (const float*)d_in[5];
    const float* W1    = (const float*)d_in[6];
    const float* W2    = (const float*)d_in[7];
    const float* phi_f = (const float*)d_in[8];
    const float* ln1g  = (const float*)d_in[9];
    const float* ln1b  = (const float*)d_in[10];
    const float* ln2g  = (const float*)d_in[11];
    const float* ln2b  = (const float*)d_in[12];
    const float* Wc    = (const float*)d_in[13];
    const float* bc    = (const float*)d_in[14];

    int dev = 0;
    cudaGetDevice(&dev);
    int sms = 148;
    cudaDeviceGetAttribute(&sms, cudaDevAttrMultiProcessorCount, dev);

    cudaFuncSetAttribute(fused, cudaFuncAttributeMaxDynamicSharedMemorySize, SMEM_BYTES);
    fused<<<sms, NT, SMEM_BYTES>>>(Wv, Wo, phi_q, W1, W2, phi_f,
                                   ln1g, ln1b, ln2g, ln2b, Wc, bc, (float4*)d_out);
}